// round 7
// baseline (speedup 1.0000x reference)
#include <cuda_runtime.h>
#include <cstdint>

// Degree accumulator scratch (N = 100000 <= 131072). Device global: no allocs.
__device__ float g_deg[131072];

// ---------------------------------------------------------------------------
// Kernel 1: zero the output accumulator (d_out, used in-place) and degrees.
// ---------------------------------------------------------------------------
__global__ void zero_kernel(float4* __restrict__ out4, int n_out4, int n_nodes) {
    int i = blockIdx.x * blockDim.x + threadIdx.x;
    if (i < n_out4) out4[i] = make_float4(0.f, 0.f, 0.f, 0.f);
    if (i < n_nodes) g_deg[i] = 0.f;
}

// ---------------------------------------------------------------------------
// Kernel 2: per-edge scatter-accumulate.
// 16 threads per edge; each lane handles one float4 (4 of the 64 features).
// Loads are fully coalesced (256B per edge row). Accumulation uses the
// sm_90+ vectorized reduction red.global.add.v4.f32 (1 instr per 16B).
// Indices are int32 (JAX demotes int64 randint without x64 enabled).
// ---------------------------------------------------------------------------
__global__ void edge_kernel(const float4* __restrict__ src_emb,   // [N,16] float4
                            const float4* __restrict__ edge_emb,  // [E,16] float4
                            const int* __restrict__ src_idx,
                            const int* __restrict__ dst_idx,
                            float* __restrict__ out,               // [N,64] floats
                            int E, int N) {
    int gtid = blockIdx.x * blockDim.x + threadIdx.x;
    int e    = gtid >> 4;
    int lane = gtid & 15;
    if (e >= E) return;

    int s = src_idx[e];
    int d = dst_idx[e];
    // Defensive clamp: turns a dtype misread into rel_err instead of a crash.
    s = min(max(s, 0), N - 1);
    d = min(max(d, 0), N - 1);

    float4 a = src_emb[(size_t)s * 16 + lane];
    float4 b = edge_emb[(size_t)e * 16 + lane];
    float4 m = make_float4(a.x + b.x, a.y + b.y, a.z + b.z, a.w + b.w);

    float* p = out + (size_t)d * 64 + lane * 4;
    asm volatile("red.global.add.v4.f32 [%0], {%1, %2, %3, %4};"
                 :: "l"(p), "f"(m.x), "f"(m.y), "f"(m.z), "f"(m.w)
                 : "memory");

    if (lane == 0) atomicAdd(&g_deg[d], 1.0f);
}

// ---------------------------------------------------------------------------
// Kernel 3: divide by max(degree, 1).
// ---------------------------------------------------------------------------
__global__ void norm_kernel(float4* __restrict__ out4, int n_nodes) {
    int gtid = blockIdx.x * blockDim.x + threadIdx.x;
    int node = gtid >> 4;
    int lane = gtid & 15;
    if (node >= n_nodes) return;

    float deg = g_deg[node];
    float inv = 1.0f / fmaxf(deg, 1.0f);
    float4 v = out4[(size_t)node * 16 + lane];
    v.x *= inv; v.y *= inv; v.z *= inv; v.w *= inv;
    out4[(size_t)node * 16 + lane] = v;
}

// ---------------------------------------------------------------------------
// Launch. Inputs (metadata order):
//   d_in[0] src_embedding  float32 [N,64]
//   d_in[1] edge_embedding float32 [E,64]
//   d_in[2] src_idx        int32   [E]   (JAX demotes int64 without x64)
//   d_in[3] dst_idx        int32   [E]
//   d_in[4] num_nodes      (scalar; unused — derive N from in_sizes[0])
// Output: float32 [N,64]
// ---------------------------------------------------------------------------
extern "C" void kernel_launch(void* const* d_in, const int* in_sizes, int n_in,
                              void* d_out, int out_size) {
    const float* src_emb  = (const float*)d_in[0];
    const float* edge_emb = (const float*)d_in[1];
    const int*   src_idx  = (const int*)d_in[2];
    const int*   dst_idx  = (const int*)d_in[3];
    float*       out      = (float*)d_out;

    const int D = 64;
    int N = in_sizes[0] / D;
    int E = in_sizes[2];  // element count of src_idx

    // 1) zero accumulators
    int n_out4 = N * (D / 4);          // 1.6M float4s
    int zthreads = n_out4 > N ? n_out4 : N;
    zero_kernel<<<(zthreads + 255) / 256, 256>>>((float4*)out, n_out4, N);

    // 2) edge scatter-add (16 threads per edge)
    long long ethreads = (long long)E * 16;
    int eblocks = (int)((ethreads + 255) / 256);
    edge_kernel<<<eblocks, 256>>>((const float4*)src_emb, (const float4*)edge_emb,
                                  src_idx, dst_idx, out, E, N);

    // 3) normalize
    long long nthreads = (long long)N * 16;
    norm_kernel<<<(int)((nthreads + 255) / 256), 256>>>((float4*)out, N);
}

// round 8
// speedup vs baseline: 1.2163x; 1.2163x over previous
#include <cuda_runtime.h>
#include <cstdint>

// ---------------------------------------------------------------------------
// Static device scratch (graph-safe; no allocations).
//   N = 100000 <= 131072, E = 1250000 <= 2097152
// ---------------------------------------------------------------------------
__device__ int  g_cnt[131072];      // per-node in-degree (kept for the divide)
__device__ int  g_cur[131072];      // scan offsets -> scatter cursors -> row ends
__device__ int  g_bsum[128];        // per-block scan totals
__device__ int2 g_edges[2097152];   // CSR payload: (edge_id, src_idx) sorted by dst

// ---------------------------------------------------------------------------
// K1: zero the histogram.
// ---------------------------------------------------------------------------
__global__ void zero_cnt_kernel(int total) {
    int i = blockIdx.x * blockDim.x + threadIdx.x;
    if (i < total) g_cnt[i] = 0;
}

// ---------------------------------------------------------------------------
// K2: histogram of dst indices.
// ---------------------------------------------------------------------------
__global__ void hist_kernel(const int* __restrict__ dst_idx, int E, int N) {
    int e = blockIdx.x * blockDim.x + threadIdx.x;
    if (e >= E) return;
    int d = min(max(dst_idx[e], 0), N - 1);
    atomicAdd(&g_cnt[d], 1);
}

// ---------------------------------------------------------------------------
// K3a: per-block exclusive scan (128 blocks x 1024). Writes block-local
// exclusive prefix into g_cur and the block total into g_bsum.
// ---------------------------------------------------------------------------
__global__ void scan_block_kernel(int N) {
    __shared__ int warp_sums[32];
    int t = threadIdx.x;
    int i = blockIdx.x * 1024 + t;
    int c = (i < N) ? g_cnt[i] : 0;

    int lane = t & 31, w = t >> 5;
    int v = c;  // inclusive warp scan
    #pragma unroll
    for (int s = 1; s < 32; s <<= 1) {
        int n = __shfl_up_sync(0xffffffffu, v, s);
        if (lane >= s) v += n;
    }
    if (lane == 31) warp_sums[w] = v;
    __syncthreads();
    if (w == 0) {
        int wv = warp_sums[lane];
        #pragma unroll
        for (int s = 1; s < 32; s <<= 1) {
            int n = __shfl_up_sync(0xffffffffu, wv, s);
            if (lane >= s) wv += n;
        }
        warp_sums[lane] = wv;  // inclusive scan of the 32 warp totals
    }
    __syncthreads();
    int warp_prefix = (w > 0) ? warp_sums[w - 1] : 0;
    g_cur[i] = warp_prefix + v - c;              // block-local exclusive prefix
    if (t == 1023) g_bsum[blockIdx.x] = warp_sums[31];  // block total
}

// ---------------------------------------------------------------------------
// K3b: add cross-block prefix. Each block tree-reduces g_bsum[0..b).
// ---------------------------------------------------------------------------
__global__ void add_prefix_kernel(int N) {
    __shared__ int sh[128];
    int t = threadIdx.x;
    int b = blockIdx.x;
    if (t < 128) sh[t] = (t < b) ? g_bsum[t] : 0;
    __syncthreads();
    #pragma unroll
    for (int s = 64; s > 0; s >>= 1) {
        if (t < s) sh[t] += sh[t + s];
        __syncthreads();
    }
    int i = b * 1024 + t;
    g_cur[i] += sh[0];
}

// ---------------------------------------------------------------------------
// K4: scatter (edge_id, src_idx) pairs into CSR order using atomic cursors.
// After this kernel g_cur[n] == row_end[n].
// ---------------------------------------------------------------------------
__global__ void scatter_kernel(const int* __restrict__ src_idx,
                               const int* __restrict__ dst_idx, int E, int N) {
    int e = blockIdx.x * blockDim.x + threadIdx.x;
    if (e >= E) return;
    int d = min(max(dst_idx[e], 0), N - 1);
    int s = min(max(src_idx[e], 0), N - 1);
    int pos = atomicAdd(&g_cur[d], 1);
    g_edges[pos] = make_int2(e, s);
}

// ---------------------------------------------------------------------------
// K5: gather + mean. 16 lanes per node; each lane owns one float4 (4 feats).
// Register accumulation; single clean store per output row; divide fused.
// ---------------------------------------------------------------------------
__global__ void gather_kernel(const float4* __restrict__ src_emb,
                              const float4* __restrict__ edge_emb,
                              float4* __restrict__ out, int N) {
    int gtid = blockIdx.x * blockDim.x + threadIdx.x;
    int node = gtid >> 4;
    int lane = gtid & 15;
    if (node >= N) return;

    int end   = g_cur[node];
    int cnt   = g_cnt[node];
    int start = end - cnt;

    float4 acc = make_float4(0.f, 0.f, 0.f, 0.f);
    #pragma unroll 4
    for (int j = start; j < end; ++j) {
        int2   ee = __ldg(&g_edges[j]);        // broadcast across the 16 lanes
        float4 a  = edge_emb[(size_t)ee.x * 16 + lane];
        float4 b  = src_emb[(size_t)ee.y * 16 + lane];
        acc.x += a.x + b.x;
        acc.y += a.y + b.y;
        acc.z += a.z + b.z;
        acc.w += a.w + b.w;
    }

    float inv = (cnt > 0) ? (1.0f / (float)cnt) : 0.0f;
    out[(size_t)node * 16 + lane] =
        make_float4(acc.x * inv, acc.y * inv, acc.z * inv, acc.w * inv);
}

// ---------------------------------------------------------------------------
// Launch. Inputs (metadata order):
//   d_in[0] src_embedding  float32 [N,64]
//   d_in[1] edge_embedding float32 [E,64]
//   d_in[2] src_idx        int32   [E]
//   d_in[3] dst_idx        int32   [E]
//   d_in[4] num_nodes      (unused; N derived from in_sizes[0])
// Output: float32 [N,64]
// ---------------------------------------------------------------------------
extern "C" void kernel_launch(void* const* d_in, const int* in_sizes, int n_in,
                              void* d_out, int out_size) {
    const float* src_emb  = (const float*)d_in[0];
    const float* edge_emb = (const float*)d_in[1];
    const int*   src_idx  = (const int*)d_in[2];
    const int*   dst_idx  = (const int*)d_in[3];
    float*       out      = (float*)d_out;

    const int D = 64;
    int N = in_sizes[0] / D;
    int E = in_sizes[2];

    // K1: zero full histogram (131072 covers any N here)
    zero_cnt_kernel<<<131072 / 256, 256>>>(131072);

    // K2: histogram of dst
    hist_kernel<<<(E + 255) / 256, 256>>>(dst_idx, E, N);

    // K3: exclusive scan (fixed 128 x 1024 covers 131072 slots)
    scan_block_kernel<<<128, 1024>>>(N);
    add_prefix_kernel<<<128, 1024>>>(N);

    // K4: scatter edges into CSR order
    scatter_kernel<<<(E + 255) / 256, 256>>>(src_idx, dst_idx, E, N);

    // K5: gather + mean (16 threads per node)
    long long gthreads = (long long)N * 16;
    gather_kernel<<<(int)((gthreads + 255) / 256), 256>>>(
        (const float4*)src_emb, (const float4*)edge_emb, (float4*)out, N);
}